// round 5
// baseline (speedup 1.0000x reference)
#include <cuda_runtime.h>
#include <cuda_fp16.h>
#include <math.h>
#include <stdint.h>

// Problem constants
#define Bn   16
#define Cc   256
#define Nn   4096
#define Hh   4
#define Dd   64
#define O3   768
#define HID  256
#define SCALE 0.125f

// Scratch: everything pre-split as half hi/lo pairs
__device__ __half g_qh[(size_t)Bn * O3 * Nn];     // 96 MB  (qkv hi)
__device__ __half g_ql[(size_t)Bn * O3 * Nn];     // 96 MB  (qkv lo)
__device__ __half g_xh[(size_t)Bn * Cc * Nn];     // 32 MB
__device__ __half g_xl[(size_t)Bn * Cc * Nn];     // 32 MB
__device__ __half g_wh[O3 * Cc];
__device__ __half g_wl[O3 * Cc];
__device__ __half g_w2h[(size_t)Bn * HID * HID];
__device__ __half g_w2l[(size_t)Bn * HID * HID];
__device__ float  g_ctxp[(size_t)Bn * Hh * 8 * Dd * Dd];   // 8 MB

// ===========================================================================
// Helpers
// ===========================================================================
__device__ __forceinline__ uint32_t smem_u32(const void* p) {
    uint32_t a;
    asm("{ .reg .u64 t; cvta.to.shared.u64 t, %1; cvt.u32.u64 %0, t; }" : "=r"(a) : "l"(p));
    return a;
}
__device__ __forceinline__ void split_h(float x, __half& h, __half& l) {
    h = __float2half_rn(x);
    l = __float2half_rn(x - __half2float(h));
}
__device__ __forceinline__ void mma16(float* d, const uint32_t* a, const uint32_t* b) {
    asm volatile(
        "mma.sync.aligned.m16n8k16.row.col.f32.f16.f16.f32 "
        "{%0,%1,%2,%3},{%4,%5,%6,%7},{%8,%9},{%0,%1,%2,%3};"
        : "+f"(d[0]), "+f"(d[1]), "+f"(d[2]), "+f"(d[3])
        : "r"(a[0]), "r"(a[1]), "r"(a[2]), "r"(a[3]), "r"(b[0]), "r"(b[1]));
}
#define LDM_X4(r, addr) \
    asm volatile("ldmatrix.sync.aligned.m8n8.x4.shared.b16 {%0,%1,%2,%3}, [%4];" \
        : "=r"((r)[0]), "=r"((r)[1]), "=r"((r)[2]), "=r"((r)[3]) : "r"(addr))
#define LDM_X4_T(r, addr) \
    asm volatile("ldmatrix.sync.aligned.m8n8.x4.trans.shared.b16 {%0,%1,%2,%3}, [%4];" \
        : "=r"((r)[0]), "=r"((r)[1]), "=r"((r)[2]), "=r"((r)[3]) : "r"(addr))
#define CP_ASYNC16(dst, src) \
    asm volatile("cp.async.cg.shared.global [%0], [%1], 16;" :: "r"(dst), "l"(src))
#define CP_COMMIT() asm volatile("cp.async.commit_group;" ::: "memory")
#define CP_WAIT(n)  asm volatile("cp.async.wait_group %0;" :: "n"(n) : "memory")

// ===========================================================================
// Split kernel: fp32 -> (hi, lo) half pair. n4 float4 groups.
// ===========================================================================
__global__ void split_kernel(const float* __restrict__ src,
                             __half* __restrict__ h, __half* __restrict__ l, int n4)
{
    int i = blockIdx.x * blockDim.x + threadIdx.x;
    if (i >= n4) return;
    float4 v = *(const float4*)(src + (size_t)i * 4);
    __half h0, l0, h1, l1;
    split_h(v.x, h0, l0); split_h(v.y, h1, l1);
    *(half2*)(h + (size_t)i * 4)     = __halves2half2(h0, h1);
    *(half2*)(l + (size_t)i * 4)     = __halves2half2(l0, l1);
    split_h(v.z, h0, l0); split_h(v.w, h1, l1);
    *(half2*)(h + (size_t)i * 4 + 2) = __halves2half2(h0, h1);
    *(half2*)(l + (size_t)i * 4 + 2) = __halves2half2(l0, l1);
}

// ===========================================================================
// gemm_h: 3-term fp16-split GEMM on pre-split inputs, cp.async pipelined.
// C[m,n] = sum_k A[m,k]*B[k,n]; A row-major [M x 256], B [256 x Nn].
// Block 128x128, BK=64 (4 slices), 8 warps = 2m x 4n (warp 64x32).
// Output: either half pair (outH/outL) or fp32 (+bias).
// ===========================================================================
#define PA_B 144                       // A smem row pitch bytes (64 halves + pad)
#define PB_B 272                       // B smem row pitch bytes (128 halves + pad)
#define A_TILE_B (128 * PA_B)          // 18432
#define B_TILE_B (64 * PB_B)           // 17408
#define STAGE_B (2 * A_TILE_B + 2 * B_TILE_B)   // 71680
#define GH_SMEM (2 * STAGE_B)          // 143360

__global__ void __launch_bounds__(256, 1)
gemm_h(const __half* __restrict__ Ah, const __half* __restrict__ Al, size_t aStride,
       const __half* __restrict__ Bh, const __half* __restrict__ Bl, size_t bStride,
       __half* __restrict__ outH, __half* __restrict__ outL,
       float* __restrict__ outF, size_t cStride,
       const float* __restrict__ bias)
{
    extern __shared__ char smem[];
    const uint32_t sb = smem_u32(smem);
    const int tid  = threadIdx.x;
    const int wid  = tid >> 5;
    const int lane = tid & 31;
    const int wm   = (wid >> 2) * 64;
    const int wn   = (wid & 3) * 32;
    const int mBlk = blockIdx.y * 128;
    const int nBlk = blockIdx.x * 128;
    const int z    = blockIdx.z;

    const __half* Agh = Ah + (size_t)z * aStride + (size_t)mBlk * Cc;
    const __half* Agl = Al + (size_t)z * aStride + (size_t)mBlk * Cc;
    const __half* Bgh = Bh + (size_t)z * bStride + nBlk;
    const __half* Bgl = Bl + (size_t)z * bStride + nBlk;

    float acc[4][4][4];
    #pragma unroll
    for (int i = 0; i < 4; i++)
        #pragma unroll
        for (int j = 0; j < 4; j++)
            #pragma unroll
            for (int r = 0; r < 4; r++) acc[i][j][r] = 0.f;

    // issue cp.async for slice s into buffer buf
    auto issue = [&](int s, int buf) {
        const int kk = s * 64;
        const uint32_t st = sb + buf * STAGE_B;
        #pragma unroll
        for (int p = 0; p < 4; p++) {
            int id = tid + p * 256;                 // A: 128 rows x 8 chunks
            int m = id >> 3, ch = id & 7;
            size_t go = (size_t)m * Cc + kk + ch * 8;
            uint32_t dst = st + m * PA_B + ch * 16;
            CP_ASYNC16(dst, Agh + go);
            CP_ASYNC16(dst + A_TILE_B, Agl + go);
        }
        #pragma unroll
        for (int p = 0; p < 4; p++) {
            int id = tid + p * 256;                 // B: 64 rows x 16 chunks
            int r = id >> 4, ch = id & 15;
            size_t go = (size_t)(kk + r) * Nn + ch * 8;
            uint32_t dst = st + 2 * A_TILE_B + r * PB_B + ch * 16;
            CP_ASYNC16(dst, Bgh + go);
            CP_ASYNC16(dst + B_TILE_B, Bgl + go);
        }
    };

    const int lr = lane & 15;
    const int lc = (lane >> 4) & 1;

    auto compute = [&](int buf) {
        const uint32_t aHb = sb + buf * STAGE_B;
        const uint32_t aLb = aHb + A_TILE_B;
        const uint32_t bHb = aLb + A_TILE_B;
        const uint32_t bLb = bHb + B_TILE_B;
        #pragma unroll
        for (int ks = 0; ks < 4; ks++) {
            uint32_t bh[2][4], bl[2][4];
            #pragma unroll
            for (int fnp = 0; fnp < 2; fnp++) {
                uint32_t off = (uint32_t)(ks * 16 + lr) * PB_B
                             + (uint32_t)(wn + fnp * 16 + lc * 8) * 2;
                LDM_X4_T(bh[fnp], bHb + off);
                LDM_X4_T(bl[fnp], bLb + off);
            }
            #pragma unroll
            for (int fm = 0; fm < 4; fm++) {
                uint32_t off = (uint32_t)(wm + fm * 16 + lr) * PA_B
                             + (uint32_t)(ks * 16 + lc * 8) * 2;
                uint32_t ah[4], al[4];
                LDM_X4(ah, aHb + off);
                LDM_X4(al, aLb + off);
                #pragma unroll
                for (int fn = 0; fn < 4; fn++) {
                    const uint32_t* bph = &bh[fn >> 1][(fn & 1) * 2];
                    const uint32_t* bpl = &bl[fn >> 1][(fn & 1) * 2];
                    mma16(acc[fm][fn], ah, bph);
                    mma16(acc[fm][fn], ah, bpl);
                    mma16(acc[fm][fn], al, bph);
                }
            }
        }
    };

    issue(0, 0); CP_COMMIT();
    issue(1, 1); CP_COMMIT();
    #pragma unroll 1
    for (int s = 0; s < 4; s++) {
        if (s < 3) { CP_WAIT(1); } else { CP_WAIT(0); }
        __syncthreads();
        compute(s & 1);
        __syncthreads();
        if (s < 2) { issue(s + 2, s & 1); CP_COMMIT(); }
    }

    // epilogue
    if (outF) {
        float* Cg = outF + (size_t)z * cStride;
        #pragma unroll
        for (int fm = 0; fm < 4; fm++) {
            int row = mBlk + wm + fm * 16 + (lane >> 2);
            float b0 = bias ? bias[row]     : 0.f;
            float b8 = bias ? bias[row + 8] : 0.f;
            #pragma unroll
            for (int fn = 0; fn < 4; fn++) {
                int col = nBlk + wn + fn * 8 + (lane & 3) * 2;
                float2 v0 = { acc[fm][fn][0] + b0, acc[fm][fn][1] + b0 };
                float2 v1 = { acc[fm][fn][2] + b8, acc[fm][fn][3] + b8 };
                *(float2*)&Cg[(size_t)row * Nn + col]       = v0;
                *(float2*)&Cg[(size_t)(row + 8) * Nn + col] = v1;
            }
        }
    } else {
        __half* Ch = outH + (size_t)z * cStride;
        __half* Cl = outL + (size_t)z * cStride;
        #pragma unroll
        for (int fm = 0; fm < 4; fm++) {
            int row = mBlk + wm + fm * 16 + (lane >> 2);
            #pragma unroll
            for (int fn = 0; fn < 4; fn++) {
                int col = nBlk + wn + fn * 8 + (lane & 3) * 2;
                __half h0, l0, h1, l1;
                split_h(acc[fm][fn][0], h0, l0); split_h(acc[fm][fn][1], h1, l1);
                *(half2*)&Ch[(size_t)row * Nn + col] = __halves2half2(h0, h1);
                *(half2*)&Cl[(size_t)row * Nn + col] = __halves2half2(l0, l1);
                split_h(acc[fm][fn][2], h0, l0); split_h(acc[fm][fn][3], h1, l1);
                *(half2*)&Ch[(size_t)(row + 8) * Nn + col] = __halves2half2(h0, h1);
                *(half2*)&Cl[(size_t)(row + 8) * Nn + col] = __halves2half2(l0, l1);
            }
        }
    }
}

// ===========================================================================
// Context partials: ctxp[bh][p][d][e] = sum_{n chunk} k_sm[d,n]*v[e,n]
// Inputs are pre-split halves. M=64(d) x N=64(e), K=512 in slices of 128.
// ===========================================================================
#define PK_B 272                          // 128 halves + pad
#define CT_B (64 * PK_B)                  // 17408 per array
#define CTX_SMEM_BYTES (4 * CT_B)         // 69632 (kH,kL,vH,vL)

__global__ void __launch_bounds__(128, 1)
context_part()
{
    extern __shared__ char smem[];
    const uint32_t sb = smem_u32(smem);
    int bh = blockIdx.x;
    int p  = blockIdx.y;
    int b = bh >> 2, h = bh & 3;
    const __half* Kh = g_qh + ((size_t)b * O3 + HID     + h * Dd) * Nn;
    const __half* Kl = g_ql + ((size_t)b * O3 + HID     + h * Dd) * Nn;
    const __half* Vh = g_qh + ((size_t)b * O3 + 2 * HID + h * Dd) * Nn;
    const __half* Vl = g_ql + ((size_t)b * O3 + 2 * HID + h * Dd) * Nn;

    const int tid  = threadIdx.x;
    const int wid  = tid >> 5;
    const int lane = tid & 31;
    const int wm = (wid >> 1) * 32;
    const int wn = (wid & 1) * 32;

    float acc[2][4][4];
    #pragma unroll
    for (int i = 0; i < 2; i++)
        #pragma unroll
        for (int j = 0; j < 4; j++)
            #pragma unroll
            for (int r = 0; r < 4; r++) acc[i][j][r] = 0.f;

    const int lr = lane & 15;
    const int lc = (lane >> 4) & 1;
    const uint32_t kHb = sb;
    const uint32_t kLb = kHb + CT_B;
    const uint32_t vHb = kLb + CT_B;
    const uint32_t vLb = vHb + CT_B;

    #pragma unroll 1
    for (int sl = 0; sl < 4; sl++) {
        const int nn = p * 512 + sl * 128;
        __syncthreads();
        #pragma unroll
        for (int q = 0; q < 8; q++) {
            int id = tid + q * 128;               // 64 rows x 16 chunks
            int row = id >> 4, ch = id & 15;
            size_t go = (size_t)row * Nn + nn + ch * 8;
            uint32_t off = row * PK_B + ch * 16;
            *(uint4*)(smem + (kHb - sb) + off) = *(const uint4*)(Kh + go);
            *(uint4*)(smem + (kLb - sb) + off) = *(const uint4*)(Kl + go);
            *(uint4*)(smem + (vHb - sb) + off) = *(const uint4*)(Vh + go);
            *(uint4*)(smem + (vLb - sb) + off) = *(const uint4*)(Vl + go);
        }
        __syncthreads();

        #pragma unroll
        for (int ks = 0; ks < 8; ks++) {
            uint32_t bhf[2][4], blf[2][4];
            #pragma unroll
            for (int fnp = 0; fnp < 2; fnp++) {
                uint32_t off = (uint32_t)(wn + fnp * 16 + lc * 8 + (lane & 7)) * PK_B
                             + (uint32_t)(ks * 32 + ((lane >> 3) & 1) * 16);
                LDM_X4(bhf[fnp], vHb + off);
                LDM_X4(blf[fnp], vLb + off);
            }
            #pragma unroll
            for (int fm = 0; fm < 2; fm++) {
                uint32_t off = (uint32_t)(wm + fm * 16 + lr) * PK_B
                             + (uint32_t)(ks * 32 + lc * 16);
                uint32_t ah[4], al[4];
                LDM_X4(ah, kHb + off);
                LDM_X4(al, kLb + off);
                #pragma unroll
                for (int fn = 0; fn < 4; fn++) {
                    const uint32_t* bph = &bhf[fn >> 1][(fn & 1) * 2];
                    const uint32_t* bpl = &blf[fn >> 1][(fn & 1) * 2];
                    mma16(acc[fm][fn], ah, bph);
                    mma16(acc[fm][fn], ah, bpl);
                    mma16(acc[fm][fn], al, bph);
                }
            }
        }
    }

    float* dst = g_ctxp + ((size_t)bh * 8 + p) * (Dd * Dd);
    #pragma unroll
    for (int fm = 0; fm < 2; fm++) {
        int d0 = wm + fm * 16 + (lane >> 2);
        #pragma unroll
        for (int fn = 0; fn < 4; fn++) {
            int e0 = wn + fn * 8 + (lane & 3) * 2;
            dst[d0 * Dd + e0]           = acc[fm][fn][0];
            dst[d0 * Dd + e0 + 1]       = acc[fm][fn][1];
            dst[(d0 + 8) * Dd + e0]     = acc[fm][fn][2];
            dst[(d0 + 8) * Dd + e0 + 1] = acc[fm][fn][3];
        }
    }
}

// ===========================================================================
// Softmax over d on q (x SCALE). Half pair in, half pair out.
// ===========================================================================
__global__ void softmax_q_kernel()
{
    int idx = blockIdx.x * blockDim.x + threadIdx.x;
    if (idx >= Bn * Hh * Nn) return;
    int n = idx & (Nn - 1);
    int h = (idx >> 12) & (Hh - 1);
    int b = idx >> 14;
    size_t base = ((size_t)b * O3 + h * Dd) * Nn + n;

    float vals[Dd];
    float mx = -INFINITY;
    #pragma unroll
    for (int d = 0; d < Dd; d++) {
        vals[d] = __half2float(g_qh[base + (size_t)d * Nn])
                + __half2float(g_ql[base + (size_t)d * Nn]);
        mx = fmaxf(mx, vals[d]);
    }
    float s = 0.f;
    #pragma unroll
    for (int d = 0; d < Dd; d++) { vals[d] = expf(vals[d] - mx); s += vals[d]; }
    float inv = SCALE / s;
    #pragma unroll
    for (int d = 0; d < Dd; d++) {
        __half hh, ll;
        split_h(vals[d] * inv, hh, ll);
        g_qh[base + (size_t)d * Nn] = hh;
        g_ql[base + (size_t)d * Nn] = ll;
    }
}

// ===========================================================================
// Softmax over n on k. Half pair in/out. One block per (b,h,d) row.
// ===========================================================================
__global__ void softmax_k_kernel()
{
    int row = blockIdx.x;
    int b = row >> 8;
    int hd = row & 255;
    size_t base = ((size_t)b * O3 + HID + hd) * Nn;

    __shared__ float red[256];
    const int tid = threadIdx.x;
    float v[16];
    float mx = -INFINITY;
    #pragma unroll
    for (int i = 0; i < 16; i++) {
        v[i] = __half2float(g_qh[base + tid + i * 256])
             + __half2float(g_ql[base + tid + i * 256]);
        mx = fmaxf(mx, v[i]);
    }
    red[tid] = mx; __syncthreads();
    for (int s = 128; s > 0; s >>= 1) { if (tid < s) red[tid] = fmaxf(red[tid], red[tid + s]); __syncthreads(); }
    mx = red[0]; __syncthreads();
    float sum = 0.f;
    #pragma unroll
    for (int i = 0; i < 16; i++) { v[i] = expf(v[i] - mx); sum += v[i]; }
    red[tid] = sum; __syncthreads();
    for (int s = 128; s > 0; s >>= 1) { if (tid < s) red[tid] += red[tid + s]; __syncthreads(); }
    float inv = 1.f / red[0];
    #pragma unroll
    for (int i = 0; i < 16; i++) {
        __half hh, ll;
        split_h(v[i] * inv, hh, ll);
        g_qh[base + tid + i * 256] = hh;
        g_ql[base + tid + i * 256] = ll;
    }
}

// ===========================================================================
// W2[b][c][h*64+d] = sum_e w_out[c][h*64+e] * ctx[bh][d][e]; writes half pair.
// ===========================================================================
__global__ void w2_kernel(const float* __restrict__ w_out)
{
    int bh = blockIdx.x;
    int b = bh >> 2, h = bh & 3;
    __shared__ float ctx[Dd * Dd];
    const int tid = threadIdx.x;

    for (int i = tid; i < Dd * Dd; i += 256) {
        float s = 0.f;
        #pragma unroll
        for (int p = 0; p < 8; p++)
            s += g_ctxp[((size_t)bh * 8 + p) * (Dd * Dd) + i];
        ctx[i] = s;
    }
    __syncthreads();

    int c = tid;
    float w[Dd];
    #pragma unroll
    for (int e = 0; e < Dd; e++) w[e] = w_out[c * HID + h * Dd + e];
    #pragma unroll 4
    for (int d = 0; d < Dd; d++) {
        float s = 0.f;
        #pragma unroll
        for (int e = 0; e < Dd; e++) s = fmaf(w[e], ctx[d * Dd + e], s);
        __half hh, ll;
        split_h(s, hh, ll);
        size_t o = ((size_t)b * HID + c) * HID + h * Dd + d;
        g_w2h[o] = hh;
        g_w2l[o] = ll;
    }
}

// ===========================================================================
extern "C" void kernel_launch(void* const* d_in, const int* in_sizes, int n_in,
                              void* d_out, int out_size)
{
    const float* x     = (const float*)d_in[0];
    const float* w_qkv = (const float*)d_in[1];
    const float* w_out = (const float*)d_in[2];
    const float* b_out = (const float*)d_in[3];
    float* out = (float*)d_out;

    __half *qh, *ql, *xh, *xl, *wh, *wl, *w2h, *w2l;
    cudaGetSymbolAddress((void**)&qh, g_qh);
    cudaGetSymbolAddress((void**)&ql, g_ql);
    cudaGetSymbolAddress((void**)&xh, g_xh);
    cudaGetSymbolAddress((void**)&xl, g_xl);
    cudaGetSymbolAddress((void**)&wh, g_wh);
    cudaGetSymbolAddress((void**)&wl, g_wl);
    cudaGetSymbolAddress((void**)&w2h, g_w2h);
    cudaGetSymbolAddress((void**)&w2l, g_w2l);

    static int attr_done = 0;
    if (!attr_done) {
        cudaFuncSetAttribute(gemm_h, cudaFuncAttributeMaxDynamicSharedMemorySize, GH_SMEM);
        cudaFuncSetAttribute(context_part, cudaFuncAttributeMaxDynamicSharedMemorySize, CTX_SMEM_BYTES);
        attr_done = 1;
    }

    // 0) pre-split x and w_qkv into half pairs
    {
        int n4 = (Bn * Cc * Nn) / 4;
        split_kernel<<<(n4 + 255) / 256, 256>>>(x, xh, xl, n4);
        int w4 = (O3 * Cc) / 4;
        split_kernel<<<(w4 + 255) / 256, 256>>>(w_qkv, wh, wl, w4);
    }
    // 1) QKV projection -> half pairs: [768,256] x [256,4096] per batch
    {
        dim3 grid(Nn / 128, O3 / 128, Bn);
        gemm_h<<<grid, 256, GH_SMEM>>>(wh, wl, 0,
                                       xh, xl, (size_t)Cc * Nn,
                                       qh, ql, nullptr, (size_t)O3 * Nn, nullptr);
    }
    // 2) softmaxes (half pair in/out)
    softmax_q_kernel<<<(Bn * Hh * Nn) / 256, 256>>>();
    softmax_k_kernel<<<Bn * Hh * Dd, 256>>>();
    // 3) context partials (tensor cores, half inputs)
    {
        dim3 grid(Bn * Hh, 8);
        context_part<<<grid, 128, CTX_SMEM_BYTES>>>();
    }
    // 4) W2 = w_out_h @ ctx_h^T -> half pairs
    w2_kernel<<<Bn * Hh, 256>>>(w_out);
    // 5) out = W2_b @ q_sm_b + bias (fp32 out)
    {
        dim3 grid(Nn / 128, HID / 128, Bn);
        gemm_h<<<grid, 256, GH_SMEM>>>(w2h, w2l, (size_t)HID * HID,
                                       qh, ql, (size_t)O3 * Nn,
                                       nullptr, nullptr, out, (size_t)HID * Nn, b_out);
    }
}

// round 6
// speedup vs baseline: 1.1882x; 1.1882x over previous
#include <cuda_runtime.h>
#include <cuda_fp16.h>
#include <math.h>
#include <stdint.h>

// Problem constants
#define Bn   16
#define Cc   256
#define Nn   4096
#define Hh   4
#define Dd   64
#define O3   768
#define HID  256
#define SCALE 0.125f

// Scratch
__device__ __half g_xh[(size_t)Bn * Cc * Nn];     // x split hi
__device__ __half g_xl[(size_t)Bn * Cc * Nn];     // x split lo
__device__ __half g_wh[O3 * Cc];
__device__ __half g_wl[O3 * Cc];
__device__ __half g_qh[(size_t)Bn * HID * Nn];    // q softmaxed, hi
__device__ __half g_ql[(size_t)Bn * HID * Nn];    // q softmaxed, lo
__device__ float  g_k [(size_t)Bn * HID * Nn];    // k pre-softmax fp32
__device__ __half g_kh[(size_t)Bn * HID * Nn];    // k softmaxed hi
__device__ __half g_kl[(size_t)Bn * HID * Nn];
__device__ __half g_vh[(size_t)Bn * HID * Nn];
__device__ __half g_vl[(size_t)Bn * HID * Nn];
__device__ float  g_ctxp[(size_t)Bn * Hh * 8 * Dd * Dd];
__device__ __half g_w2h[(size_t)Bn * HID * HID];
__device__ __half g_w2l[(size_t)Bn * HID * HID];

// ===========================================================================
// Helpers
// ===========================================================================
__device__ __forceinline__ uint32_t smem_u32(const void* p) {
    uint32_t a;
    asm("{ .reg .u64 t; cvta.to.shared.u64 t, %1; cvt.u32.u64 %0, t; }" : "=r"(a) : "l"(p));
    return a;
}
__device__ __forceinline__ void split_h(float x, __half& h, __half& l) {
    h = __float2half_rn(x);
    l = __float2half_rn(x - __half2float(h));
}
__device__ __forceinline__ void mma16(float* d, const uint32_t* a, const uint32_t* b) {
    asm volatile(
        "mma.sync.aligned.m16n8k16.row.col.f32.f16.f16.f32 "
        "{%0,%1,%2,%3},{%4,%5,%6,%7},{%8,%9},{%0,%1,%2,%3};"
        : "+f"(d[0]), "+f"(d[1]), "+f"(d[2]), "+f"(d[3])
        : "r"(a[0]), "r"(a[1]), "r"(a[2]), "r"(a[3]), "r"(b[0]), "r"(b[1]));
}
#define LDM_X4(r, addr) \
    asm volatile("ldmatrix.sync.aligned.m8n8.x4.shared.b16 {%0,%1,%2,%3}, [%4];" \
        : "=r"((r)[0]), "=r"((r)[1]), "=r"((r)[2]), "=r"((r)[3]) : "r"(addr))
#define LDM_X4_T(r, addr) \
    asm volatile("ldmatrix.sync.aligned.m8n8.x4.trans.shared.b16 {%0,%1,%2,%3}, [%4];" \
        : "=r"((r)[0]), "=r"((r)[1]), "=r"((r)[2]), "=r"((r)[3]) : "r"(addr))
#define CP_ASYNC16(dst, src) \
    asm volatile("cp.async.cg.shared.global [%0], [%1], 16;" :: "r"(dst), "l"(src))
#define CP_COMMIT() asm volatile("cp.async.commit_group;" ::: "memory")
#define CP_WAIT(n)  asm volatile("cp.async.wait_group %0;" :: "n"(n) : "memory")

// ===========================================================================
// Split kernel: fp32 -> (hi, lo) half pair
// ===========================================================================
__global__ void split_kernel(const float* __restrict__ src,
                             __half* __restrict__ h, __half* __restrict__ l, int n4)
{
    int i = blockIdx.x * blockDim.x + threadIdx.x;
    if (i >= n4) return;
    float4 v = *(const float4*)(src + (size_t)i * 4);
    __half h0, l0, h1, l1;
    split_h(v.x, h0, l0); split_h(v.y, h1, l1);
    *(half2*)(h + (size_t)i * 4)     = __halves2half2(h0, h1);
    *(half2*)(l + (size_t)i * 4)     = __halves2half2(l0, l1);
    split_h(v.z, h0, l0); split_h(v.w, h1, l1);
    *(half2*)(h + (size_t)i * 4 + 2) = __halves2half2(h0, h1);
    *(half2*)(l + (size_t)i * 4 + 2) = __halves2half2(l0, l1);
}

// ===========================================================================
// fused_gemm: 3-term fp16-split GEMM, pre-split inputs, cp.async 3-stage.
// C[m,n] = sum_k A[m,k]*B[k,n].  K=256 fixed (8 slices of 32).
// Block tile 128x128, 8 warps = 2m x 4n, 2 CTAs/SM.
// mode 0 (GEMM1): epilogue by blockIdx.y: y<2 q(softmax_d->half pair),
//                 y<4 k(fp32), else v(half pair).
// mode 1 (GEMM2): fp32 out + bias.
// ===========================================================================
#define PA_B 80                          // A smem row pitch bytes (32 halves+pad)
#define PB_B 272                         // B smem row pitch bytes (128 halves+pad)
#define A_ST (128 * PA_B)                // 10240
#define B_ST (32 * PB_B)                 // 8704
#define STG  (2 * A_ST + 2 * B_ST)       // 37888 per stage
#define NSTAGE 3
#define FG_SMEM (NSTAGE * STG)           // 113664

__global__ void __launch_bounds__(256, 2)
fused_gemm(const __half* __restrict__ Ah, const __half* __restrict__ Al, size_t aStride,
           const __half* __restrict__ Bh, const __half* __restrict__ Bl, size_t bStride,
           int mode, const float* __restrict__ bias, float* __restrict__ outF)
{
    extern __shared__ char smem[];
    const uint32_t sb = smem_u32(smem);
    const int tid  = threadIdx.x;
    const int wid  = tid >> 5;
    const int lane = tid & 31;
    const int wm   = (wid >> 2) * 64;
    const int wn   = (wid & 3) * 32;
    const int mBlk = blockIdx.y * 128;
    const int nBlk = blockIdx.x * 128;
    const int z    = blockIdx.z;

    const __half* Agh = Ah + (size_t)z * aStride + (size_t)mBlk * 256;
    const __half* Agl = Al + (size_t)z * aStride + (size_t)mBlk * 256;
    const __half* Bgh = Bh + (size_t)z * bStride + nBlk;
    const __half* Bgl = Bl + (size_t)z * bStride + nBlk;

    float acc[4][4][4];
    #pragma unroll
    for (int i = 0; i < 4; i++)
        #pragma unroll
        for (int j = 0; j < 4; j++)
            #pragma unroll
            for (int r = 0; r < 4; r++) acc[i][j][r] = 0.f;

    auto issue = [&](int s, int buf) {
        const int kk = s * 32;
        const uint32_t st = sb + buf * STG;
        #pragma unroll
        for (int p = 0; p < 2; p++) {            // A: 128 rows x 4 chunks
            int id = tid + p * 256;
            int m = id >> 2, ch = id & 3;
            size_t go = (size_t)m * 256 + kk + ch * 8;
            uint32_t dst = st + m * PA_B + ch * 16;
            CP_ASYNC16(dst, Agh + go);
            CP_ASYNC16(dst + A_ST, Agl + go);
        }
        #pragma unroll
        for (int p = 0; p < 2; p++) {            // B: 32 rows x 16 chunks
            int id = tid + p * 256;
            int r = id >> 4, ch = id & 15;
            size_t go = (size_t)(kk + r) * Nn + ch * 8;
            uint32_t dst = st + 2 * A_ST + r * PB_B + ch * 16;
            CP_ASYNC16(dst, Bgh + go);
            CP_ASYNC16(dst + B_ST, Bgl + go);
        }
    };

    const int lr = lane & 15;
    const int lc = (lane >> 4) & 1;

    auto compute = [&](int buf) {
        const uint32_t aHb = sb + buf * STG;
        const uint32_t aLb = aHb + A_ST;
        const uint32_t bHb = aLb + A_ST;
        const uint32_t bLb = bHb + B_ST;
        #pragma unroll
        for (int ks = 0; ks < 2; ks++) {
            uint32_t bh[2][4], bl[2][4];
            #pragma unroll
            for (int fnp = 0; fnp < 2; fnp++) {
                uint32_t off = (uint32_t)(ks * 16 + lr) * PB_B
                             + (uint32_t)(wn + fnp * 16 + lc * 8) * 2;
                LDM_X4_T(bh[fnp], bHb + off);
                LDM_X4_T(bl[fnp], bLb + off);
            }
            #pragma unroll
            for (int fm = 0; fm < 4; fm++) {
                uint32_t off = (uint32_t)(wm + fm * 16 + lr) * PA_B
                             + (uint32_t)(ks * 16 + lc * 8) * 2;
                uint32_t ah[4], al[4];
                LDM_X4(ah, aHb + off);
                LDM_X4(al, aLb + off);
                #pragma unroll
                for (int fn = 0; fn < 4; fn++) {
                    const uint32_t* bph = &bh[fn >> 1][(fn & 1) * 2];
                    const uint32_t* bpl = &bl[fn >> 1][(fn & 1) * 2];
                    mma16(acc[fm][fn], ah, bph);
                    mma16(acc[fm][fn], ah, bpl);
                    mma16(acc[fm][fn], al, bph);
                }
            }
        }
    };

    issue(0, 0); CP_COMMIT();
    issue(1, 1); CP_COMMIT();
    #pragma unroll 1
    for (int s = 0; s < 8; s++) {
        if (s < 7) { CP_WAIT(1); } else { CP_WAIT(0); }
        __syncthreads();
        if (s + 2 < 8) { issue(s + 2, (s + 2) % 3); CP_COMMIT(); }
        compute(s % 3);
    }

    // ------------------------------ epilogues ------------------------------
    if (mode == 1) {
        float* Cg = outF + (size_t)z * HID * Nn;
        #pragma unroll
        for (int fm = 0; fm < 4; fm++) {
            int row = mBlk + wm + fm * 16 + (lane >> 2);
            float b0 = bias[row], b8 = bias[row + 8];
            #pragma unroll
            for (int fn = 0; fn < 4; fn++) {
                int col = nBlk + wn + fn * 8 + (lane & 3) * 2;
                float2 v0 = { acc[fm][fn][0] + b0, acc[fm][fn][1] + b0 };
                float2 v1 = { acc[fm][fn][2] + b8, acc[fm][fn][3] + b8 };
                *(float2*)&Cg[(size_t)row * Nn + col]       = v0;
                *(float2*)&Cg[(size_t)(row + 8) * Nn + col] = v1;
            }
        }
        return;
    }

    const int y = blockIdx.y;
    if (y >= 4) {            // V: half pairs, direct
        int vBase = mBlk - 512;
        __half* Vh = g_vh + ((size_t)z * HID + vBase) * Nn;
        __half* Vl = g_vl + ((size_t)z * HID + vBase) * Nn;
        #pragma unroll
        for (int fm = 0; fm < 4; fm++) {
            int row = wm + fm * 16 + (lane >> 2);
            #pragma unroll
            for (int fn = 0; fn < 4; fn++) {
                int col = nBlk + wn + fn * 8 + (lane & 3) * 2;
                __half h0, l0, h1, l1;
                split_h(acc[fm][fn][0], h0, l0); split_h(acc[fm][fn][1], h1, l1);
                *(half2*)&Vh[(size_t)row * Nn + col] = __halves2half2(h0, h1);
                *(half2*)&Vl[(size_t)row * Nn + col] = __halves2half2(l0, l1);
                split_h(acc[fm][fn][2], h0, l0); split_h(acc[fm][fn][3], h1, l1);
                *(half2*)&Vh[(size_t)(row + 8) * Nn + col] = __halves2half2(h0, h1);
                *(half2*)&Vl[(size_t)(row + 8) * Nn + col] = __halves2half2(l0, l1);
            }
        }
        return;
    }
    if (y >= 2) {            // K: fp32 for later softmax over n
        int kBase = mBlk - 256;
        float* Kg = g_k + ((size_t)z * HID + kBase) * Nn;
        #pragma unroll
        for (int fm = 0; fm < 4; fm++) {
            int row = wm + fm * 16 + (lane >> 2);
            #pragma unroll
            for (int fn = 0; fn < 4; fn++) {
                int col = nBlk + wn + fn * 8 + (lane & 3) * 2;
                float2 v0 = { acc[fm][fn][0], acc[fm][fn][1] };
                float2 v1 = { acc[fm][fn][2], acc[fm][fn][3] };
                *(float2*)&Kg[(size_t)row * Nn + col]       = v0;
                *(float2*)&Kg[(size_t)(row + 8) * Nn + col] = v1;
            }
        }
        return;
    }

    // Q: fused softmax over d (64 rows/head, 2 heads per 128-row tile), xSCALE
    {
        float* S = (float*)smem;            // [128][132] fp32
        float* cInv = (float*)(smem + 128 * 132 * 4);   // [256]
        __syncthreads();                    // main loop smem use done
        #pragma unroll
        for (int fm = 0; fm < 4; fm++) {
            int row = wm + fm * 16 + (lane >> 2);
            #pragma unroll
            for (int fn = 0; fn < 4; fn++) {
                int col = wn + fn * 8 + (lane & 3) * 2;
                *(float2*)&S[row * 132 + col]       = make_float2(acc[fm][fn][0], acc[fm][fn][1]);
                *(float2*)&S[(row + 8) * 132 + col] = make_float2(acc[fm][fn][2], acc[fm][fn][3]);
            }
        }
        __syncthreads();

        // column reduce: thread = half(64 rows) x col
        {
            int colI = tid & 127;
            int hf   = tid >> 7;
            float mx = -INFINITY;
            #pragma unroll 4
            for (int r = 0; r < 64; r++)
                mx = fmaxf(mx, S[(hf * 64 + r) * 132 + colI]);
            float sum = 0.f;
            #pragma unroll 4
            for (int r = 0; r < 64; r++) {
                float e = __expf(S[(hf * 64 + r) * 132 + colI] - mx);
                S[(hf * 64 + r) * 132 + colI] = e;
                sum += e;
            }
            cInv[tid] = SCALE / sum;
        }
        __syncthreads();

        // scale + split + write, coalesced
        __half* Qh = g_qh + ((size_t)z * HID + mBlk) * Nn + nBlk;
        __half* Ql = g_ql + ((size_t)z * HID + mBlk) * Nn + nBlk;
        int c2   = (tid & 63) * 2;
        int rgrp = tid >> 6;
        #pragma unroll 4
        for (int rr = 0; rr < 32; rr++) {
            int row = rgrp * 32 + rr;
            int ci  = ((row >> 6) << 7) | c2;
            float2 v = *(float2*)&S[row * 132 + c2];
            float e0 = v.x * cInv[ci];
            float e1 = v.y * cInv[ci + 1];
            __half h0, l0, h1, l1;
            split_h(e0, h0, l0); split_h(e1, h1, l1);
            *(half2*)&Qh[(size_t)row * Nn + c2] = __halves2half2(h0, h1);
            *(half2*)&Ql[(size_t)row * Nn + c2] = __halves2half2(l0, l1);
        }
    }
}

// ===========================================================================
// Softmax over n on k: fp32 in -> half pairs out. One block per (b,hd) row.
// ===========================================================================
__global__ void softmax_k_kernel()
{
    int row = blockIdx.x;                  // Bn*HID = 4096
    size_t base = (size_t)row * Nn;
    const float* src = g_k + base;

    __shared__ float red[256];
    const int tid = threadIdx.x;
    float v[16];
    float mx = -INFINITY;
    #pragma unroll
    for (int i = 0; i < 16; i++) { v[i] = src[tid + i * 256]; mx = fmaxf(mx, v[i]); }
    red[tid] = mx; __syncthreads();
    for (int s = 128; s > 0; s >>= 1) { if (tid < s) red[tid] = fmaxf(red[tid], red[tid + s]); __syncthreads(); }
    mx = red[0]; __syncthreads();
    float sum = 0.f;
    #pragma unroll
    for (int i = 0; i < 16; i++) { v[i] = __expf(v[i] - mx); sum += v[i]; }
    red[tid] = sum; __syncthreads();
    for (int s = 128; s > 0; s >>= 1) { if (tid < s) red[tid] += red[tid + s]; __syncthreads(); }
    float inv = 1.f / red[0];
    #pragma unroll
    for (int i = 0; i < 16; i++) {
        __half hh, ll;
        split_h(v[i] * inv, hh, ll);
        g_kh[base + tid + i * 256] = hh;
        g_kl[base + tid + i * 256] = ll;
    }
}

// ===========================================================================
// Context partials: ctxp[bh][p][d][e] = sum_{n chunk} k_sm[d,n]*v[e,n]
// ===========================================================================
#define PK_B 272
#define CT_B (64 * PK_B)
#define CTX_SMEM_BYTES (4 * CT_B)

__global__ void __launch_bounds__(128, 2)
context_part()
{
    extern __shared__ char smem[];
    const uint32_t sb = smem_u32(smem);
    int bh = blockIdx.x;
    int p  = blockIdx.y;
    int b = bh >> 2, h = bh & 3;
    const __half* Kh = g_kh + ((size_t)b * HID + h * Dd) * Nn;
    const __half* Kl = g_kl + ((size_t)b * HID + h * Dd) * Nn;
    const __half* Vh = g_vh + ((size_t)b * HID + h * Dd) * Nn;
    const __half* Vl = g_vl + ((size_t)b * HID + h * Dd) * Nn;

    const int tid  = threadIdx.x;
    const int wid  = tid >> 5;
    const int lane = tid & 31;
    const int wm = (wid >> 1) * 32;
    const int wn = (wid & 1) * 32;

    float acc[2][4][4];
    #pragma unroll
    for (int i = 0; i < 2; i++)
        #pragma unroll
        for (int j = 0; j < 4; j++)
            #pragma unroll
            for (int r = 0; r < 4; r++) acc[i][j][r] = 0.f;

    const int lr = lane & 15;
    const int lc = (lane >> 4) & 1;
    const uint32_t kHb = sb;
    const uint32_t kLb = kHb + CT_B;
    const uint32_t vHb = kLb + CT_B;
    const uint32_t vLb = vHb + CT_B;

    #pragma unroll 1
    for (int sl = 0; sl < 4; sl++) {
        const int nn = p * 512 + sl * 128;
        __syncthreads();
        #pragma unroll
        for (int q = 0; q < 8; q++) {
            int id = tid + q * 128;
            int row = id >> 4, ch = id & 15;
            size_t go = (size_t)row * Nn + nn + ch * 8;
            uint32_t off = row * PK_B + ch * 16;
            CP_ASYNC16(kHb + off, Kh + go);
            CP_ASYNC16(kLb + off, Kl + go);
            CP_ASYNC16(vHb + off, Vh + go);
            CP_ASYNC16(vLb + off, Vl + go);
        }
        CP_COMMIT();
        CP_WAIT(0);
        __syncthreads();

        #pragma unroll
        for (int ks = 0; ks < 8; ks++) {
            uint32_t bhf[2][4], blf[2][4];
            #pragma unroll
            for (int fnp = 0; fnp < 2; fnp++) {
                uint32_t off = (uint32_t)(wn + fnp * 16 + lc * 8 + (lane & 7)) * PK_B
                             + (uint32_t)(ks * 32 + ((lane >> 3) & 1) * 16);
                LDM_X4(bhf[fnp], vHb + off);
                LDM_X4(blf[fnp], vLb + off);
            }
            #pragma unroll
            for (int fm = 0; fm < 2; fm++) {
                uint32_t off = (uint32_t)(wm + fm * 16 + lr) * PK_B
                             + (uint32_t)(ks * 32 + lc * 16);
                uint32_t ah[4], al[4];
                LDM_X4(ah, kHb + off);
                LDM_X4(al, kLb + off);
                #pragma unroll
                for (int fn = 0; fn < 4; fn++) {
                    const uint32_t* bph = &bhf[fn >> 1][(fn & 1) * 2];
                    const uint32_t* bpl = &blf[fn >> 1][(fn & 1) * 2];
                    mma16(acc[fm][fn], ah, bph);
                    mma16(acc[fm][fn], ah, bpl);
                    mma16(acc[fm][fn], al, bph);
                }
            }
        }
    }

    float* dst = g_ctxp + ((size_t)bh * 8 + p) * (Dd * Dd);
    #pragma unroll
    for (int fm = 0; fm < 2; fm++) {
        int d0 = wm + fm * 16 + (lane >> 2);
        #pragma unroll
        for (int fn = 0; fn < 4; fn++) {
            int e0 = wn + fn * 8 + (lane & 3) * 2;
            dst[d0 * Dd + e0]           = acc[fm][fn][0];
            dst[d0 * Dd + e0 + 1]       = acc[fm][fn][1];
            dst[(d0 + 8) * Dd + e0]     = acc[fm][fn][2];
            dst[(d0 + 8) * Dd + e0 + 1] = acc[fm][fn][3];
        }
    }
}

// ===========================================================================
// W2[b][c][h*64+d] = sum_e w_out[c][h*64+e] * ctx[bh][d][e]; half pairs out.
// ===========================================================================
__global__ void w2_kernel(const float* __restrict__ w_out)
{
    int bh = blockIdx.x;
    int b = bh >> 2, h = bh & 3;
    __shared__ float ctx[Dd * Dd];
    const int tid = threadIdx.x;

    for (int i = tid; i < Dd * Dd; i += 256) {
        float s = 0.f;
        #pragma unroll
        for (int p = 0; p < 8; p++)
            s += g_ctxp[((size_t)bh * 8 + p) * (Dd * Dd) + i];
        ctx[i] = s;
    }
    __syncthreads();

    int c = tid;
    float w[Dd];
    #pragma unroll
    for (int e = 0; e < Dd; e++) w[e] = w_out[c * HID + h * Dd + e];
    #pragma unroll 4
    for (int d = 0; d < Dd; d++) {
        float s = 0.f;
        #pragma unroll
        for (int e = 0; e < Dd; e++) s = fmaf(w[e], ctx[d * Dd + e], s);
        __half hh, ll;
        split_h(s, hh, ll);
        size_t o = ((size_t)b * HID + c) * HID + h * Dd + d;
        g_w2h[o] = hh;
        g_w2l[o] = ll;
    }
}

// ===========================================================================
extern "C" void kernel_launch(void* const* d_in, const int* in_sizes, int n_in,
                              void* d_out, int out_size)
{
    const float* x     = (const float*)d_in[0];
    const float* w_qkv = (const float*)d_in[1];
    const float* w_out = (const float*)d_in[2];
    const float* b_out = (const float*)d_in[3];
    float* out = (float*)d_out;

    __half *xh, *xl, *wh, *wl, *qh, *ql, *w2h, *w2l;
    cudaGetSymbolAddress((void**)&xh, g_xh);
    cudaGetSymbolAddress((void**)&xl, g_xl);
    cudaGetSymbolAddress((void**)&wh, g_wh);
    cudaGetSymbolAddress((void**)&wl, g_wl);
    cudaGetSymbolAddress((void**)&qh, g_qh);
    cudaGetSymbolAddress((void**)&ql, g_ql);
    cudaGetSymbolAddress((void**)&w2h, g_w2h);
    cudaGetSymbolAddress((void**)&w2l, g_w2l);

    static int attr_done = 0;
    if (!attr_done) {
        cudaFuncSetAttribute(fused_gemm, cudaFuncAttributeMaxDynamicSharedMemorySize, FG_SMEM);
        cudaFuncSetAttribute(context_part, cudaFuncAttributeMaxDynamicSharedMemorySize, CTX_SMEM_BYTES);
        attr_done = 1;
    }

    // 0) pre-split x and w_qkv
    {
        int n4 = (Bn * Cc * Nn) / 4;
        split_kernel<<<(n4 + 255) / 256, 256>>>(x, xh, xl, n4);
        int w4 = (O3 * Cc) / 4;
        split_kernel<<<(w4 + 255) / 256, 256>>>(w_qkv, wh, wl, w4);
    }
    // 1) GEMM1 with fused per-section epilogues (q softmax, k fp32, v halves)
    {
        dim3 grid(Nn / 128, O3 / 128, Bn);
        fused_gemm<<<grid, 256, FG_SMEM>>>(wh, wl, 0,
                                           xh, xl, (size_t)Cc * Nn,
                                           0, nullptr, nullptr);
    }
    // 2) softmax over n on k -> half pairs
    softmax_k_kernel<<<Bn * HID, 256>>>();
    // 3) context partials
    {
        dim3 grid(Bn * Hh, 8);
        context_part<<<grid, 128, CTX_SMEM_BYTES>>>();
    }
    // 4) W2 = w_out_h @ ctx_h^T -> half pairs
    w2_kernel<<<Bn * Hh, 256>>>(w_out);
    // 5) GEMM2: out = W2_b @ q_sm_b + bias
    {
        dim3 grid(Nn / 128, HID / 128, Bn);
        fused_gemm<<<grid, 256, FG_SMEM>>>(w2h, w2l, (size_t)HID * HID,
                                           qh, ql, (size_t)HID * Nn,
                                           1, b_out, out);
    }
}